// round 7
// baseline (speedup 1.0000x reference)
#include <cuda_runtime.h>
#include <cuda_fp16.h>
#include <cstdint>

#define N_ROWS 32768
#define D      64
#define K      1024
#define BLK    128
#define NBLK   (N_ROWS / BLK)          // 256 CTAs
#define NCH    64                      // codewords per chunk
#define NCHUNK (K / NCH)               // 16

#define OFF_QUANT 0
#define OFF_ENC   ((size_t)N_ROWS * D)
#define OFF_IDX   (OFF_ENC + (size_t)N_ROWS * K)
#define OFF_LOSS  (OFF_IDX + (size_t)N_ROWS)

// smem (floats): esq[1024] | buf0[2048] | buf1[2048] | xtile[128*68]
#define SMF_ESQ  0
#define SMF_BUF  1024
#define SMF_X    (1024 + 4096)
#define XSTRIDE  68
#define SMEM_SZ  ((SMF_X + 128 * XSTRIDE) * 4)   // 55296 B

// fragment-packed codebook, plain fp16:
// index [nt_global(128)][ks(4)][lane(32)] -> uint2 {h2(d0,d0+1), h2(d0+8,d0+9)}
__device__ uint2 g_b0[128 * 4 * 32];
__device__ float g_et [K * D];           // exact emb^T [k][d]
__device__ float g_esq[K];
__device__ unsigned long long g_loss;

__device__ __forceinline__ uint32_t smem_u32(const void* p) {
    uint32_t a;
    asm("{ .reg .u64 t; cvta.to.shared.u64 t, %1; cvt.u32.u64 %0, t; }"
        : "=r"(a) : "l"(p));
    return a;
}
__device__ __forceinline__ uint32_t packh2(float a, float b) {
    __half2 h = __floats2half2_rn(a, b);   // a -> low half (smaller k index)
    return *(uint32_t*)&h;
}

#define CP16(dst, src) asm volatile( \
    "cp.async.cg.shared.global [%0], [%1], 16;" :: "r"(dst), "l"(src) : "memory")
#define CP_COMMIT() asm volatile("cp.async.commit_group;" ::: "memory")
#define CP_WAIT(n)  asm volatile("cp.async.wait_group %0;" :: "n"(n) : "memory")

#define LDS64(r0, r1, addr) asm volatile( \
    "ld.shared.v2.b32 {%0,%1}, [%2];" : "=r"(r0), "=r"(r1) : "r"(addr))

#define MMAF16(Cp, Ap, B0, B1) asm volatile( \
    "mma.sync.aligned.m16n8k16.row.col.f32.f16.f16.f32 " \
    "{%0,%1,%2,%3},{%4,%5,%6,%7},{%8,%9},{%0,%1,%2,%3};" \
    : "+f"((Cp)[0]), "+f"((Cp)[1]), "+f"((Cp)[2]), "+f"((Cp)[3]) \
    : "r"((Ap)[0]), "r"((Ap)[1]), "r"((Ap)[2]), "r"((Ap)[3]), \
      "r"(B0), "r"(B1))

// ---------------- prep: exact e^T + ||e||^2 --------------------------------
__global__ void prep_et(const float* __restrict__ emb) {
    int k = blockIdx.x * blockDim.x + threadIdx.x;
    if (k == 0) g_loss = 0ull;
    if (k >= K) return;
    float s = 0.f;
    #pragma unroll
    for (int d = 0; d < D; d++) {
        float v = emb[d * K + k];
        g_et[k * D + d] = v;
        s = fmaf(v, v, s);
    }
    g_esq[k] = s;
}

// ---------------- prep: fp16 fragment packing ------------------------------
__global__ void prep_frag(const float* __restrict__ emb) {
    int idx = blockIdx.x * blockDim.x + threadIdx.x;   // 0..16383
    if (idx >= 128 * 4 * 32) return;
    int lane = idx & 31;
    int ks   = (idx >> 5) & 3;
    int nt   = idx >> 7;
    int cw   = nt * 8 + (lane >> 2);
    int d0   = ks * 16 + (lane & 3) * 2;
    g_b0[idx] = make_uint2(
        packh2(emb[(d0    ) * K + cw], emb[(d0 + 1) * K + cw]),
        packh2(emb[(d0 + 8) * K + cw], emb[(d0 + 9) * K + cw]));
}

// ---------------- staging: 8KB linear copy per chunk -----------------------
__device__ __forceinline__ void stage_chunk(uint32_t bufb, int c, int tid) {
    const char* s0 = (const char*)(g_b0 + (size_t)c * 1024);
    #pragma unroll
    for (int i = 0; i < 4; i++) {
        uint32_t o = (uint32_t)(i * BLK + tid) * 16;
        CP16(bufb + o, s0 + o);
    }
    CP_COMMIT();
}

__device__ __forceinline__ bool sless(float s, int i, float S, int I) {
    return (s < S) || (s == S && i < I);
}

// ---------------- main ------------------------------------------------------
__global__ __launch_bounds__(BLK, 2) void vq_mma(const float* __restrict__ x,
                                                 float* __restrict__ out) {
    extern __shared__ __align__(16) float smem[];
    const uint32_t smb = smem_u32(smem);
    float* esq_s = smem + SMF_ESQ;
    float* xs    = smem + SMF_X;
    const int tid  = threadIdx.x;
    const int wid  = tid >> 5, lane = tid & 31;
    const int r0   = lane >> 2, c0 = lane & 3;
    const int rowbase = blockIdx.x * BLK;

    stage_chunk(smb + SMF_BUF * 4, 0, tid);

    #pragma unroll
    for (int i = 0; i < K / BLK; i++)
        esq_s[i * BLK + tid] = g_esq[i * BLK + tid];

    // stage x tile (raw floats, stride 68 => conflict-free row reads)
    {
        const float4* xg = (const float4*)(x + (size_t)rowbase * D);
        #pragma unroll
        for (int i = 0; i < 16; i++) {
            int idx = i * BLK + tid;
            int r = idx >> 4, d4 = idx & 15;
            *(float4*)(xs + r * XSTRIDE + d4 * 4) = xg[idx];
        }
    }
    __syncthreads();

    // A fragments in registers: fp16(-2x). slot = (mt*4+ks)*4 + p
    uint32_t ay[32];
    #pragma unroll
    for (int mt = 0; mt < 2; mt++)
      #pragma unroll
      for (int ks = 0; ks < 4; ks++)
        #pragma unroll
        for (int p = 0; p < 4; p++) {
            int r = wid * 32 + mt * 16 + r0 + (p & 1) * 8;
            int d = ks * 16 + c0 * 2 + (p >> 1) * 8;
            ay[(mt * 4 + ks) * 4 + p] =
                packh2(-2.f * xs[r * XSTRIDE + d], -2.f * xs[r * XSTRIDE + d + 1]);
        }

    // per-slot approx top-4 (ascending); slot sl = mt*2 + (q>>1)
    float ts[4][4];
    int   ti[4][4];
    #pragma unroll
    for (int s = 0; s < 4; s++)
        #pragma unroll
        for (int j = 0; j < 4; j++) { ts[s][j] = 3.4e38f; ti[s][j] = 0; }

    #pragma unroll 1
    for (int c = 0; c < NCHUNK; c++) {
        if (c + 1 < NCHUNK) {
            stage_chunk(smb + (SMF_BUF + ((c + 1) & 1) * 2048) * 4, c + 1, tid);
            CP_WAIT(1);
        } else {
            CP_WAIT(0);
        }
        __syncthreads();

        // encodings zero-fill for this chunk's 64 columns
        {
            float4 z = make_float4(0.f, 0.f, 0.f, 0.f);
            float* enc = out + OFF_ENC + (size_t)rowbase * K + (size_t)c * NCH;
            #pragma unroll
            for (int j = 0; j < 16; j++) {
                int idx = j * BLK + tid;
                *(float4*)(enc + (size_t)(idx >> 4) * K + (idx & 15) * 4) = z;
            }
        }

        const uint32_t bufb = smb + (SMF_BUF + (c & 1) * 2048) * 4;

        float C[2][8][4];
        #pragma unroll
        for (int mt = 0; mt < 2; mt++)
            #pragma unroll
            for (int nt = 0; nt < 8; nt++)
                #pragma unroll
                for (int q = 0; q < 4; q++) C[mt][nt][q] = 0.f;

        #pragma unroll
        for (int ks = 0; ks < 4; ks++) {
            uint32_t ba[8], bb[8];
            #pragma unroll
            for (int nt = 0; nt < 8; nt++) {
                uint32_t a = bufb + (uint32_t)(((nt * 4 + ks) * 32 + lane) * 8);
                LDS64(ba[nt], bb[nt], a);
            }
            #pragma unroll
            for (int mt = 0; mt < 2; mt++) {
                const uint32_t* ap = ay + (mt * 4 + ks) * 4;
                #pragma unroll
                for (int nt = 0; nt < 8; nt++)
                    MMAF16(C[mt][nt], ap, ba[nt], bb[nt]);
            }
        }

        // epilogue: approx score + top-4 insert (cols ascending, strict <)
        #pragma unroll
        for (int mt = 0; mt < 2; mt++)
            #pragma unroll
            for (int nt = 0; nt < 8; nt++)
                #pragma unroll
                for (int q = 0; q < 4; q++) {
                    int col = c * NCH + nt * 8 + c0 * 2 + (q & 1);
                    float sc = C[mt][nt][q] + esq_s[col];
                    int sl = mt * 2 + (q >> 1);
                    if (sc < ts[sl][3]) {
                        if (sc < ts[sl][1]) {
                            ts[sl][3] = ts[sl][2]; ti[sl][3] = ti[sl][2];
                            ts[sl][2] = ts[sl][1]; ti[sl][2] = ti[sl][1];
                            if (sc < ts[sl][0]) {
                                ts[sl][1] = ts[sl][0]; ti[sl][1] = ti[sl][0];
                                ts[sl][0] = sc; ti[sl][0] = col;
                            } else {
                                ts[sl][1] = sc; ti[sl][1] = col;
                            }
                        } else {
                            if (sc < ts[sl][2]) {
                                ts[sl][3] = ts[sl][2]; ti[sl][3] = ti[sl][2];
                                ts[sl][2] = sc; ti[sl][2] = col;
                            } else {
                                ts[sl][3] = sc; ti[sl][3] = col;
                            }
                        }
                    }
                }
        __syncthreads();
    }

    // ---- exact rescue: fp32 rescore of 16 candidates/row (4 per lane) ----
    int* rowtab = (int*)(smem + SMF_BUF);
    #pragma unroll
    for (int sl = 0; sl < 4; sl++) {
        int r = wid * 32 + (sl >> 1) * 16 + (sl & 1) * 8 + r0;
        const float4* xp = (const float4*)(xs + r * XSTRIDE);
        const float4* e0p = (const float4*)(g_et + (size_t)ti[sl][0] * D);
        const float4* e1p = (const float4*)(g_et + (size_t)ti[sl][1] * D);
        const float4* e2p = (const float4*)(g_et + (size_t)ti[sl][2] * D);
        const float4* e3p = (const float4*)(g_et + (size_t)ti[sl][3] * D);
        float d0 = 0.f, d1 = 0.f, d2 = 0.f, d3 = 0.f;
        #pragma unroll
        for (int i = 0; i < 16; i++) {
            float4 xv = xp[i];
            float4 e0 = e0p[i], e1 = e1p[i], e2 = e2p[i], e3 = e3p[i];
            d0 = fmaf(xv.x, e0.x, d0); d0 = fmaf(xv.y, e0.y, d0);
            d0 = fmaf(xv.z, e0.z, d0); d0 = fmaf(xv.w, e0.w, d0);
            d1 = fmaf(xv.x, e1.x, d1); d1 = fmaf(xv.y, e1.y, d1);
            d1 = fmaf(xv.z, e1.z, d1); d1 = fmaf(xv.w, e1.w, d1);
            d2 = fmaf(xv.x, e2.x, d2); d2 = fmaf(xv.y, e2.y, d2);
            d2 = fmaf(xv.z, e2.z, d2); d2 = fmaf(xv.w, e2.w, d2);
            d3 = fmaf(xv.x, e3.x, d3); d3 = fmaf(xv.y, e3.y, d3);
            d3 = fmaf(xv.z, e3.z, d3); d3 = fmaf(xv.w, e3.w, d3);
        }
        float sa = fmaf(-2.f, d0, esq_s[ti[sl][0]]);
        float sb = fmaf(-2.f, d1, esq_s[ti[sl][1]]);
        float sc2 = fmaf(-2.f, d2, esq_s[ti[sl][2]]);
        float sd = fmaf(-2.f, d3, esq_s[ti[sl][3]]);
        float bs = sa; int bidx = ti[sl][0];
        if (sless(sb, ti[sl][1], bs, bidx)) { bs = sb; bidx = ti[sl][1]; }
        if (sless(sc2, ti[sl][2], bs, bidx)) { bs = sc2; bidx = ti[sl][2]; }
        if (sless(sd, ti[sl][3], bs, bidx)) { bs = sd; bidx = ti[sl][3]; }
        // lex-merge exact best across the 4 lanes of the quad
        #pragma unroll
        for (int off = 1; off <= 2; off <<= 1) {
            float os = __shfl_xor_sync(0xFFFFFFFF, bs, off);
            int   oi = __shfl_xor_sync(0xFFFFFFFF, bidx, off);
            if (sless(os, oi, bs, bidx)) { bs = os; bidx = oi; }
        }
        if (c0 == 0) rowtab[r] = bidx;
    }
    __syncthreads();

    // ---- final per-row outputs: quantized, loss, index, one-hot ----------
    const int row = rowbase + tid;
    const int bi  = rowtab[tid];
    float ls = 0.f;
    {
        const float4* xp = (const float4*)(xs + tid * XSTRIDE);
        const float4* ep = (const float4*)(g_et + (size_t)bi * D);
        float4* qp = (float4*)(out + OFF_QUANT + (size_t)row * D);
        #pragma unroll
        for (int i = 0; i < D / 4; i++) {
            float4 e = ep[i], xv = xp[i];
            qp[i] = e;
            float a0 = e.x - xv.x, a1 = e.y - xv.y;
            float a2 = e.z - xv.z, a3 = e.w - xv.w;
            ls = fmaf(a0, a0, ls); ls = fmaf(a1, a1, ls);
            ls = fmaf(a2, a2, ls); ls = fmaf(a3, a3, ls);
        }
    }
    #pragma unroll
    for (int off = 16; off > 0; off >>= 1)
        ls += __shfl_xor_sync(0xFFFFFFFF, ls, off);
    if (lane == 0)   // fixed-point accumulate: order-independent => deterministic
        atomicAdd(&g_loss, (unsigned long long)__float2ll_rn(ls * 16777216.0f));

    out[OFF_IDX + row] = (float)bi;
    out[OFF_ENC + (size_t)row * K + bi] = 1.0f;
}

__global__ void loss_finalize(float* __restrict__ out) {
    out[OFF_LOSS] = (float)((double)g_loss
                  / (16777216.0 * (double)N_ROWS * (double)D));
}

extern "C" void kernel_launch(void* const* d_in, const int* in_sizes, int n_in,
                              void* d_out, int out_size) {
    const float* x   = (const float*)d_in[0];   // [8,4096,64]
    const float* emb = (const float*)d_in[1];   // [64,1024]
    float* out = (float*)d_out;

    cudaFuncSetAttribute(vq_mma, cudaFuncAttributeMaxDynamicSharedMemorySize,
                         SMEM_SZ);
    prep_et<<<(K + 255) / 256, 256>>>(emb);
    prep_frag<<<64, 256>>>(emb);
    vq_mma<<<NBLK, BLK, SMEM_SZ>>>(x, out);
    loss_finalize<<<1, 1>>>(out);
}

// round 8
// speedup vs baseline: 1.3622x; 1.3622x over previous
#include <cuda_runtime.h>
#include <cuda_fp16.h>
#include <cstdint>

#define N_ROWS 32768
#define D      64
#define K      1024
#define NTHR   256                     // 8 warps per CTA
#define ROWS_CTA 128
#define NBLK   (N_ROWS / ROWS_CTA)     // 256 CTAs
#define NCH    64                      // codewords per chunk
#define NCHUNK (K / NCH)               // 16

#define OFF_QUANT 0
#define OFF_ENC   ((size_t)N_ROWS * D)
#define OFF_IDX   (OFF_ENC + (size_t)N_ROWS * K)
#define OFF_LOSS  (OFF_IDX + (size_t)N_ROWS)

// smem (floats): esq[1024] | buf0[4096] | buf1[4096] | xtile[128*68]
#define SMF_ESQ  0
#define SMF_BUF  1024
#define SMF_X    (1024 + 8192)
#define XSTRIDE  68
#define SMEM_SZ  ((SMF_X + 128 * XSTRIDE) * 4)   // 71680 B -> 2 CTAs/SM

// fragment-packed codebook, fp16 2-term split (hi / lo):
// index [nt_global(128)][ks(4)][lane(32)] -> uint2 {h2(d0,d0+1), h2(d0+8,d0+9)}
__device__ uint2 g_b0[128 * 4 * 32];
__device__ uint2 g_b1[128 * 4 * 32];
__device__ float g_et [K * D];           // exact emb^T [k][d]
__device__ float g_esq[K];
__device__ unsigned long long g_loss;

__device__ __forceinline__ uint32_t smem_u32(const void* p) {
    uint32_t a;
    asm("{ .reg .u64 t; cvta.to.shared.u64 t, %1; cvt.u32.u64 %0, t; }"
        : "=r"(a) : "l"(p));
    return a;
}
__device__ __forceinline__ uint32_t packh2(float a, float b) {
    __half2 h = __floats2half2_rn(a, b);   // a -> low half (smaller k index)
    return *(uint32_t*)&h;
}

#define CP16(dst, src) asm volatile( \
    "cp.async.cg.shared.global [%0], [%1], 16;" :: "r"(dst), "l"(src) : "memory")
#define CP_COMMIT() asm volatile("cp.async.commit_group;" ::: "memory")
#define CP_WAIT(n)  asm volatile("cp.async.wait_group %0;" :: "n"(n) : "memory")

#define LDS64(r0, r1, addr) asm volatile( \
    "ld.shared.v2.b32 {%0,%1}, [%2];" : "=r"(r0), "=r"(r1) : "r"(addr))

#define MMAF16(Cp, Ap, B0, B1) asm volatile( \
    "mma.sync.aligned.m16n8k16.row.col.f32.f16.f16.f32 " \
    "{%0,%1,%2,%3},{%4,%5,%6,%7},{%8,%9},{%0,%1,%2,%3};" \
    : "+f"((Cp)[0]), "+f"((Cp)[1]), "+f"((Cp)[2]), "+f"((Cp)[3]) \
    : "r"((Ap)[0]), "r"((Ap)[1]), "r"((Ap)[2]), "r"((Ap)[3]), \
      "r"(B0), "r"(B1))

// ---------------- prep: exact e^T + ||e||^2 --------------------------------
__global__ void prep_et(const float* __restrict__ emb) {
    int k = blockIdx.x * blockDim.x + threadIdx.x;
    if (k == 0) g_loss = 0ull;
    if (k >= K) return;
    float s = 0.f;
    #pragma unroll
    for (int d = 0; d < D; d++) {
        float v = emb[d * K + k];
        g_et[k * D + d] = v;
        s = fmaf(v, v, s);
    }
    g_esq[k] = s;
}

// ---------------- prep: fp16 hi/lo fragment packing ------------------------
__global__ void prep_frag(const float* __restrict__ emb) {
    int idx = blockIdx.x * blockDim.x + threadIdx.x;   // 0..16383
    if (idx >= 128 * 4 * 32) return;
    int lane = idx & 31;
    int ks   = (idx >> 5) & 3;
    int nt   = idx >> 7;
    int cw   = nt * 8 + (lane >> 2);
    int d0   = ks * 16 + (lane & 3) * 2;
    float v[4];
    v[0] = emb[(d0    ) * K + cw];
    v[1] = emb[(d0 + 1) * K + cw];
    v[2] = emb[(d0 + 8) * K + cw];
    v[3] = emb[(d0 + 9) * K + cw];
    float h0[4], h1[4];
    #pragma unroll
    for (int j = 0; j < 4; j++) {
        h0[j] = __half2float(__float2half_rn(v[j]));
        h1[j] = v[j] - h0[j];
    }
    g_b0[idx] = make_uint2(packh2(h0[0], h0[1]), packh2(h0[2], h0[3]));
    g_b1[idx] = make_uint2(packh2(h1[0], h1[1]), packh2(h1[2], h1[3]));
}

// dummy: aligns ncu's "-s 5 -c 1" window onto vq_mma
__global__ void dummy_k() {}

// ---------------- staging: 8KB+8KB linear copy per chunk -------------------
__device__ __forceinline__ void stage_chunk(uint32_t bufb, int c, int tid) {
    const char* s0 = (const char*)(g_b0 + (size_t)c * 1024);
    const char* s1 = (const char*)(g_b1 + (size_t)c * 1024);
    #pragma unroll
    for (int i = 0; i < 2; i++) {
        uint32_t o = (uint32_t)(i * NTHR + tid) * 16;
        CP16(bufb + o,        s0 + o);
        CP16(bufb + 8192 + o, s1 + o);
    }
    CP_COMMIT();
}

__device__ __forceinline__ bool sless(float s, int i, float S, int I) {
    return (s < S) || (s == S && i < I);
}

// ---------------- main ------------------------------------------------------
__global__ __launch_bounds__(NTHR, 2) void vq_mma(const float* __restrict__ x,
                                                  float* __restrict__ out) {
    extern __shared__ __align__(16) float smem[];
    const uint32_t smb = smem_u32(smem);
    float* esq_s = smem + SMF_ESQ;
    float* xs    = smem + SMF_X;
    const int tid  = threadIdx.x;
    const int wid  = tid >> 5, lane = tid & 31;
    const int r0   = lane >> 2, c0 = lane & 3;
    const int rowbase = blockIdx.x * ROWS_CTA;

    stage_chunk(smb + SMF_BUF * 4, 0, tid);

    #pragma unroll
    for (int i = 0; i < K / NTHR; i++)
        esq_s[i * NTHR + tid] = g_esq[i * NTHR + tid];

    // stage x tile (raw floats, stride 68 => conflict-free row reads)
    {
        const float4* xg = (const float4*)(x + (size_t)rowbase * D);
        #pragma unroll
        for (int i = 0; i < 8; i++) {
            int idx = i * NTHR + tid;
            int r = idx >> 4, d4 = idx & 15;
            *(float4*)(xs + r * XSTRIDE + d4 * 4) = xg[idx];
        }
    }
    __syncthreads();

    // A fragments in registers: y = -2x, split y = y0 + y1 (fp16).
    // Warp owns rows [wid*16, wid*16+16). slot = ks*4 + p.
    uint32_t ay0[16], ay1[16];
    #pragma unroll
    for (int ks = 0; ks < 4; ks++)
        #pragma unroll
        for (int p = 0; p < 4; p++) {
            int r = wid * 16 + r0 + (p & 1) * 8;
            int d = ks * 16 + c0 * 2 + (p >> 1) * 8;
            float va = -2.f * xs[r * XSTRIDE + d];
            float vb = -2.f * xs[r * XSTRIDE + d + 1];
            float ha = __half2float(__float2half_rn(va));
            float hb = __half2float(__float2half_rn(vb));
            ay0[ks * 4 + p] = packh2(ha, hb);
            ay1[ks * 4 + p] = packh2(va - ha, vb - hb);
        }

    // per-slot approx top-2; slot = q>>1 (row r0 / r0+8)
    float s1[2], s2[2];
    int   i1[2], i2[2];
    #pragma unroll
    for (int s = 0; s < 2; s++) { s1[s] = s2[s] = 3.4e38f; i1[s] = i2[s] = 0; }

    #pragma unroll 1
    for (int c = 0; c < NCHUNK; c++) {
        if (c + 1 < NCHUNK) {
            stage_chunk(smb + (SMF_BUF + ((c + 1) & 1) * 4096) * 4, c + 1, tid);
            CP_WAIT(1);
        } else {
            CP_WAIT(0);
        }
        __syncthreads();   // buf[c] visible

        // encodings zero-fill for this chunk's 64 columns
        {
            float4 z = make_float4(0.f, 0.f, 0.f, 0.f);
            float* enc = out + OFF_ENC + (size_t)rowbase * K + (size_t)c * NCH;
            #pragma unroll
            for (int j = 0; j < 8; j++) {
                int idx = j * NTHR + tid;
                *(float4*)(enc + (size_t)(idx >> 4) * K + (idx & 15) * 4) = z;
            }
        }

        const uint32_t bufb = smb + (SMF_BUF + (c & 1) * 4096) * 4;

        float C[8][4];
        #pragma unroll
        for (int nt = 0; nt < 8; nt++)
            #pragma unroll
            for (int q = 0; q < 4; q++) C[nt][q] = 0.f;

        #pragma unroll
        for (int ks = 0; ks < 4; ks++) {
            uint32_t b0a[8], b0b[8], b1a[8], b1b[8];
            #pragma unroll
            for (int nt = 0; nt < 8; nt++) {
                uint32_t a = bufb + (uint32_t)(((nt * 4 + ks) * 32 + lane) * 8);
                LDS64(b0a[nt], b0b[nt], a);
                LDS64(b1a[nt], b1b[nt], a + 8192);
            }
            const uint32_t* a0 = ay0 + ks * 4;
            const uint32_t* a1 = ay1 + ks * 4;
            #pragma unroll
            for (int nt = 0; nt < 8; nt++) {
                MMAF16(C[nt], a0, b0a[nt], b0b[nt]);  // y0*e0
                MMAF16(C[nt], a0, b1a[nt], b1b[nt]);  // y0*e1
                MMAF16(C[nt], a1, b0a[nt], b0b[nt]);  // y1*e0
            }
        }

        // epilogue: sc = C + ||e||^2 ; per-slot top-2 (cols ascending)
        #pragma unroll
        for (int nt = 0; nt < 8; nt++)
            #pragma unroll
            for (int q = 0; q < 4; q++) {
                int col = c * NCH + nt * 8 + c0 * 2 + (q & 1);
                float sc = C[nt][q] + esq_s[col];
                int sl = q >> 1;
                if (sc < s1[sl]) {
                    s2[sl] = s1[sl]; i2[sl] = i1[sl];
                    s1[sl] = sc;     i1[sl] = col;
                } else if (sc < s2[sl]) {
                    s2[sl] = sc; i2[sl] = col;
                }
            }
        __syncthreads();   // buf[c] reads done before restage
    }

    // quad-merge top-2 across the 4 lanes sharing each row
    #pragma unroll
    for (int sl = 0; sl < 2; sl++) {
        #pragma unroll
        for (int off = 1; off <= 2; off <<= 1) {
            float os1 = __shfl_xor_sync(0xFFFFFFFF, s1[sl], off);
            int   oi1 = __shfl_xor_sync(0xFFFFFFFF, i1[sl], off);
            float os2 = __shfl_xor_sync(0xFFFFFFFF, s2[sl], off);
            int   oi2 = __shfl_xor_sync(0xFFFFFFFF, i2[sl], off);
            if (sless(os1, oi1, s1[sl], i1[sl])) {
                if (sless(s1[sl], i1[sl], os2, oi2)) {
                    s2[sl] = s1[sl]; i2[sl] = i1[sl];
                } else {
                    s2[sl] = os2; i2[sl] = oi2;
                }
                s1[sl] = os1; i1[sl] = oi1;
            } else if (sless(os1, oi1, s2[sl], i2[sl])) {
                s2[sl] = os1; i2[sl] = oi1;
            }
        }
    }
    int2* rowtab = (int2*)(smem + SMF_BUF);
    if (c0 == 0) {
        #pragma unroll
        for (int sl = 0; sl < 2; sl++)
            rowtab[wid * 16 + sl * 8 + r0] = make_int2(i1[sl], i2[sl]);
    }
    __syncthreads();

    // final per-row epilogue (threads 0..127): exact fp32 rescore of top-2
    if (tid < ROWS_CTA) {
        const int row = rowbase + tid;
        int ca = rowtab[tid].x, cb = rowtab[tid].y;
        const float4* xp = (const float4*)(xs + tid * XSTRIDE);
        float da = 0.f, db = 0.f;
        {
            const float4* ea = (const float4*)(g_et + (size_t)ca * D);
            const float4* eb = (const float4*)(g_et + (size_t)cb * D);
            #pragma unroll
            for (int i = 0; i < 16; i++) {
                float4 xv = xp[i], e1v = ea[i], e2v = eb[i];
                da = fmaf(xv.x, e1v.x, da); da = fmaf(xv.y, e1v.y, da);
                da = fmaf(xv.z, e1v.z, da); da = fmaf(xv.w, e1v.w, da);
                db = fmaf(xv.x, e2v.x, db); db = fmaf(xv.y, e2v.y, db);
                db = fmaf(xv.z, e2v.z, db); db = fmaf(xv.w, e2v.w, db);
            }
        }
        float sa = fmaf(-2.f, da, esq_s[ca]);
        float sb = fmaf(-2.f, db, esq_s[cb]);
        int bi = sless(sb, cb, sa, ca) ? cb : ca;

        float ls = 0.f;
        {
            const float4* ep = (const float4*)(g_et + (size_t)bi * D);
            float4* qp = (float4*)(out + OFF_QUANT + (size_t)row * D);
            #pragma unroll
            for (int i = 0; i < 16; i++) {
                float4 e = ep[i], xv = xp[i];
                qp[i] = e;
                float a0 = e.x - xv.x, a1 = e.y - xv.y;
                float a2 = e.z - xv.z, a3 = e.w - xv.w;
                ls = fmaf(a0, a0, ls); ls = fmaf(a1, a1, ls);
                ls = fmaf(a2, a2, ls); ls = fmaf(a3, a3, ls);
            }
        }
        #pragma unroll
        for (int off = 16; off > 0; off >>= 1)
            ls += __shfl_xor_sync(0xFFFFFFFF, ls, off);
        if (lane == 0)   // fixed-point accumulate: deterministic
            atomicAdd(&g_loss,
                      (unsigned long long)__float2ll_rn(ls * 16777216.0f));

        out[OFF_IDX + row] = (float)bi;
        out[OFF_ENC + (size_t)row * K + bi] = 1.0f;
    }
}

__global__ void loss_finalize(float* __restrict__ out) {
    out[OFF_LOSS] = (float)((double)g_loss
                  / (16777216.0 * (double)N_ROWS * (double)D));
}

extern "C" void kernel_launch(void* const* d_in, const int* in_sizes, int n_in,
                              void* d_out, int out_size) {
    const float* x   = (const float*)d_in[0];   // [8,4096,64]
    const float* emb = (const float*)d_in[1];   // [64,1024]
    float* out = (float*)d_out;

    cudaFuncSetAttribute(vq_mma, cudaFuncAttributeMaxDynamicSharedMemorySize,
                         SMEM_SZ);
    prep_et<<<(K + 255) / 256, 256>>>(emb);     // launch 0
    prep_frag<<<64, 256>>>(emb);                // launch 1
    dummy_k<<<1, 32>>>();                       // launch 2
    dummy_k<<<1, 32>>>();                       // launch 3
    dummy_k<<<1, 32>>>();                       // launch 4
    vq_mma<<<NBLK, NTHR, SMEM_SZ>>>(x, out);    // launch 5  <- ncu -s 5 -c 1
    loss_finalize<<<1, 1>>>(out);               // launch 6
}

// round 10
// speedup vs baseline: 1.4754x; 1.0831x over previous
#include <cuda_runtime.h>
#include <cuda_fp16.h>
#include <cstdint>

#define N_ROWS 32768
#define D      64
#define K      1024
#define NTHR   256                     // 8 warps per CTA
#define ROWS_CTA 128
#define NBLK   (N_ROWS / ROWS_CTA)     // 256 CTAs
#define NCH    64                      // codewords per chunk
#define NCHUNK (K / NCH)               // 16

#define OFF_QUANT 0
#define OFF_ENC   ((size_t)N_ROWS * D)
#define OFF_IDX   (OFF_ENC + (size_t)N_ROWS * K)
#define OFF_LOSS  (OFF_IDX + (size_t)N_ROWS)

// smem (floats): esq[1024] | buf0[4096] | buf1[4096] | xtile[128*68] | warploss[8]
#define SMF_ESQ  0
#define SMF_BUF  1024
#define SMF_X    (1024 + 8192)
#define XSTRIDE  68
#define SMF_WL   (SMF_X + 128 * XSTRIDE)
#define SMEM_SZ  ((SMF_WL + 8) * 4)              // 71712 B -> 2 CTAs/SM

// fragment-packed codebook, fp16 2-term split (hi / lo):
// index [nt_global(128)][ks(4)][lane(32)] -> uint2 {h2(d0,d0+1), h2(d0+8,d0+9)}
// total per array: 16384 uint2 = 128 KB (streamed in 8KB chunks)
__device__ uint2 g_b0[128 * 4 * 32];
__device__ uint2 g_b1[128 * 4 * 32];
__device__ float g_et [K * D];           // exact emb^T [k][d]
__device__ float g_esq[K];
__device__ unsigned long long g_loss;
__device__ unsigned int g_done;          // wraps to 0 each launch (atomicInc)

__device__ __forceinline__ uint32_t smem_u32(const void* p) {
    uint32_t a;
    asm("{ .reg .u64 t; cvta.to.shared.u64 t, %1; cvt.u32.u64 %0, t; }"
        : "=r"(a) : "l"(p));
    return a;
}
__device__ __forceinline__ uint32_t packh2(float a, float b) {
    __half2 h = __floats2half2_rn(a, b);   // a -> low half (smaller k index)
    return *(uint32_t*)&h;
}

#define CP16(dst, src) asm volatile( \
    "cp.async.cg.shared.global [%0], [%1], 16;" :: "r"(dst), "l"(src) : "memory")
#define CP_COMMIT() asm volatile("cp.async.commit_group;" ::: "memory")
#define CP_WAIT(n)  asm volatile("cp.async.wait_group %0;" :: "n"(n) : "memory")

#define LDS64(r0, r1, addr) asm volatile( \
    "ld.shared.v2.b32 {%0,%1}, [%2];" : "=r"(r0), "=r"(r1) : "r"(addr))

#define MMAF16(Cp, Ap, B0, B1) asm volatile( \
    "mma.sync.aligned.m16n8k16.row.col.f32.f16.f16.f32 " \
    "{%0,%1,%2,%3},{%4,%5,%6,%7},{%8,%9},{%0,%1,%2,%3};" \
    : "+f"((Cp)[0]), "+f"((Cp)[1]), "+f"((Cp)[2]), "+f"((Cp)[3]) \
    : "r"((Ap)[0]), "r"((Ap)[1]), "r"((Ap)[2]), "r"((Ap)[3]), \
      "r"(B0), "r"(B1))

// ---------------- fused prep: e^T, ||e||^2, fp16 hi/lo fragments -----------
__global__ void prep_all(const float* __restrict__ emb) {
    int idx = blockIdx.x * blockDim.x + threadIdx.x;   // 0..16383
    if (idx == 0) g_loss = 0ull;
    {
        int lane = idx & 31;
        int ks   = (idx >> 5) & 3;
        int nt   = idx >> 7;
        int cw   = nt * 8 + (lane >> 2);
        int d0   = ks * 16 + (lane & 3) * 2;
        float v[4];
        v[0] = emb[(d0    ) * K + cw];
        v[1] = emb[(d0 + 1) * K + cw];
        v[2] = emb[(d0 + 8) * K + cw];
        v[3] = emb[(d0 + 9) * K + cw];
        float h0[4], h1[4];
        #pragma unroll
        for (int j = 0; j < 4; j++) {
            h0[j] = __half2float(__float2half_rn(v[j]));
            h1[j] = v[j] - h0[j];
        }
        g_b0[idx] = make_uint2(packh2(h0[0], h0[1]), packh2(h0[2], h0[3]));
        g_b1[idx] = make_uint2(packh2(h1[0], h1[1]), packh2(h1[2], h1[3]));
    }
    if (idx < K) {
        float s = 0.f;
        #pragma unroll
        for (int d = 0; d < D; d++) {
            float v = emb[d * K + idx];
            g_et[idx * D + d] = v;
            s = fmaf(v, v, s);
        }
        g_esq[idx] = s;
    }
}

// ---------------- staging: 8KB+8KB linear copy per chunk -------------------
__device__ __forceinline__ void stage_chunk(uint32_t bufb, int c, int tid) {
    const char* s0 = (const char*)(g_b0 + (size_t)c * 1024);
    const char* s1 = (const char*)(g_b1 + (size_t)c * 1024);
    #pragma unroll
    for (int i = 0; i < 2; i++) {
        uint32_t o = (uint32_t)(i * NTHR + tid) * 16;
        CP16(bufb + o,        s0 + o);
        CP16(bufb + 8192 + o, s1 + o);
    }
    CP_COMMIT();
}

__device__ __forceinline__ bool sless(float s, int i, float S, int I) {
    return (s < S) || (s == S && i < I);
}

// ---------------- main ------------------------------------------------------
__global__ __launch_bounds__(NTHR, 2) void vq_mma(const float* __restrict__ x,
                                                  float* __restrict__ out) {
    extern __shared__ __align__(16) float smem[];
    const uint32_t smb = smem_u32(smem);
    float* esq_s = smem + SMF_ESQ;
    float* xs    = smem + SMF_X;
    const int tid  = threadIdx.x;
    const int wid  = tid >> 5, lane = tid & 31;
    const int r0   = lane >> 2, c0 = lane & 3;
    const int rowbase = blockIdx.x * ROWS_CTA;

    stage_chunk(smb + SMF_BUF * 4, 0, tid);

    #pragma unroll
    for (int i = 0; i < K / NTHR; i++)
        esq_s[i * NTHR + tid] = g_esq[i * NTHR + tid];

    // stage x tile (raw floats, stride 68 => conflict-free row reads)
    {
        const float4* xg = (const float4*)(x + (size_t)rowbase * D);
        #pragma unroll
        for (int i = 0; i < 8; i++) {
            int idx = i * NTHR + tid;
            int r = idx >> 4, d4 = idx & 15;
            *(float4*)(xs + r * XSTRIDE + d4 * 4) = xg[idx];
        }
    }
    __syncthreads();

    // A fragments in registers: y = -2x, split y = y0 + y1 (fp16).
    // Warp owns rows [wid*16, wid*16+16). slot = ks*4 + p.
    uint32_t ay0[16], ay1[16];
    #pragma unroll
    for (int ks = 0; ks < 4; ks++)
        #pragma unroll
        for (int p = 0; p < 4; p++) {
            int r = wid * 16 + r0 + (p & 1) * 8;
            int d = ks * 16 + c0 * 2 + (p >> 1) * 8;
            float va = -2.f * xs[r * XSTRIDE + d];
            float vb = -2.f * xs[r * XSTRIDE + d + 1];
            float ha = __half2float(__float2half_rn(va));
            float hb = __half2float(__float2half_rn(vb));
            ay0[ks * 4 + p] = packh2(ha, hb);
            ay1[ks * 4 + p] = packh2(va - ha, vb - hb);
        }

    // per-slot approx top-2; slot = q>>1 (row r0 / r0+8)
    float s1[2], s2[2];
    int   i1[2], i2[2];
    #pragma unroll
    for (int s = 0; s < 2; s++) { s1[s] = s2[s] = 3.4e38f; i1[s] = i2[s] = 0; }

    #pragma unroll 1
    for (int c = 0; c < NCHUNK; c++) {
        if (c + 1 < NCHUNK) {
            stage_chunk(smb + (SMF_BUF + ((c + 1) & 1) * 4096) * 4, c + 1, tid);
            CP_WAIT(1);
        } else {
            CP_WAIT(0);
        }
        __syncthreads();   // buf[c] visible

        // encodings zero-fill for this chunk's 64 columns
        {
            float4 z = make_float4(0.f, 0.f, 0.f, 0.f);
            float* enc = out + OFF_ENC + (size_t)rowbase * K + (size_t)c * NCH;
            #pragma unroll
            for (int j = 0; j < 8; j++) {
                int idx = j * NTHR + tid;
                *(float4*)(enc + (size_t)(idx >> 4) * K + (idx & 15) * 4) = z;
            }
        }

        const uint32_t bufb = smb + (SMF_BUF + (c & 1) * 4096) * 4;

        float C[8][4];
        #pragma unroll
        for (int nt = 0; nt < 8; nt++)
            #pragma unroll
            for (int q = 0; q < 4; q++) C[nt][q] = 0.f;

        #pragma unroll
        for (int ks = 0; ks < 4; ks++) {
            uint32_t b0a[8], b0b[8], b1a[8], b1b[8];
            #pragma unroll
            for (int nt = 0; nt < 8; nt++) {
                uint32_t a = bufb + (uint32_t)(((nt * 4 + ks) * 32 + lane) * 8);
                LDS64(b0a[nt], b0b[nt], a);
                LDS64(b1a[nt], b1b[nt], a + 8192);
            }
            const uint32_t* a0 = ay0 + ks * 4;
            const uint32_t* a1 = ay1 + ks * 4;
            #pragma unroll
            for (int nt = 0; nt < 8; nt++) {
                MMAF16(C[nt], a0, b0a[nt], b0b[nt]);  // y0*e0
                MMAF16(C[nt], a0, b1a[nt], b1b[nt]);  // y0*e1
                MMAF16(C[nt], a1, b0a[nt], b0b[nt]);  // y1*e0
            }
        }

        // epilogue: sc = C + ||e||^2 ; per-slot top-2 (cols ascending)
        #pragma unroll
        for (int nt = 0; nt < 8; nt++)
            #pragma unroll
            for (int q = 0; q < 4; q++) {
                int col = c * NCH + nt * 8 + c0 * 2 + (q & 1);
                float sc = C[nt][q] + esq_s[col];
                int sl = q >> 1;
                if (sc < s1[sl]) {
                    s2[sl] = s1[sl]; i2[sl] = i1[sl];
                    s1[sl] = sc;     i1[sl] = col;
                } else if (sc < s2[sl]) {
                    s2[sl] = sc; i2[sl] = col;
                }
            }
        __syncthreads();   // buf[c] reads done before restage
    }

    // quad-merge top-2 across the 4 lanes sharing each row
    #pragma unroll
    for (int sl = 0; sl < 2; sl++) {
        #pragma unroll
        for (int off = 1; off <= 2; off <<= 1) {
            float os1 = __shfl_xor_sync(0xFFFFFFFF, s1[sl], off);
            int   oi1 = __shfl_xor_sync(0xFFFFFFFF, i1[sl], off);
            float os2 = __shfl_xor_sync(0xFFFFFFFF, s2[sl], off);
            int   oi2 = __shfl_xor_sync(0xFFFFFFFF, i2[sl], off);
            if (sless(os1, oi1, s1[sl], i1[sl])) {
                if (sless(s1[sl], i1[sl], os2, oi2)) {
                    s2[sl] = s1[sl]; i2[sl] = i1[sl];
                } else {
                    s2[sl] = os2; i2[sl] = oi2;
                }
                s1[sl] = os1; i1[sl] = oi1;
            } else if (sless(os1, oi1, s2[sl], i2[sl])) {
                s2[sl] = os1; i2[sl] = oi1;
            }
        }
    }
    int2* rowtab = (int2*)(smem + SMF_BUF);
    if (c0 == 0) {
        #pragma unroll
        for (int sl = 0; sl < 2; sl++)
            rowtab[wid * 16 + sl * 8 + r0] = make_int2(i1[sl], i2[sl]);
    }
    __syncthreads();

    // final per-row epilogue (threads 0..127): exact fp32 rescore of top-2
    long long* wl = (long long*)(smem + SMF_WL);
    if (tid < ROWS_CTA) {
        const int row = rowbase + tid;
        int ca = rowtab[tid].x, cb = rowtab[tid].y;
        const float4* xp = (const float4*)(xs + tid * XSTRIDE);
        float da = 0.f, db = 0.f;
        {
            const float4* ea = (const float4*)(g_et + (size_t)ca * D);
            const float4* eb = (const float4*)(g_et + (size_t)cb * D);
            #pragma unroll
            for (int i = 0; i < 16; i++) {
                float4 xv = xp[i], e1v = ea[i], e2v = eb[i];
                da = fmaf(xv.x, e1v.x, da); da = fmaf(xv.y, e1v.y, da);
                da = fmaf(xv.z, e1v.z, da); da = fmaf(xv.w, e1v.w, da);
                db = fmaf(xv.x, e2v.x, db); db = fmaf(xv.y, e2v.y, db);
                db = fmaf(xv.z, e2v.z, db); db = fmaf(xv.w, e2v.w, db);
            }
        }
        float sa = fmaf(-2.f, da, esq_s[ca]);
        float sb = fmaf(-2.f, db, esq_s[cb]);
        int bi = sless(sb, cb, sa, ca) ? cb : ca;

        float ls = 0.f;
        {
            const float4* ep = (const float4*)(g_et + (size_t)bi * D);
            float4* qp = (float4*)(out + OFF_QUANT + (size_t)row * D);
            #pragma unroll
            for (int i = 0; i < 16; i++) {
                float4 e = ep[i], xv = xp[i];
                qp[i] = e;
                float a0 = e.x - xv.x, a1 = e.y - xv.y;
                float a2 = e.z - xv.z, a3 = e.w - xv.w;
                ls = fmaf(a0, a0, ls); ls = fmaf(a1, a1, ls);
                ls = fmaf(a2, a2, ls); ls = fmaf(a3, a3, ls);
            }
        }
        #pragma unroll
        for (int off = 16; off > 0; off >>= 1)
            ls += __shfl_xor_sync(0xFFFFFFFF, ls, off);
        if (lane == 0)   // fixed-point warp partial -> smem (deterministic)
            wl[wid] = (long long)__float2ll_rn(ls * 16777216.0f);

        out[OFF_IDX + row] = (float)bi;
        out[OFF_ENC + (size_t)row * K + bi] = 1.0f;
    }
    __syncthreads();

    // tid 0: single fenced g_loss add, then last-CTA-done finalize
    if (tid == 0) {
        long long csum = wl[0] + wl[1] + wl[2] + wl[3];
        atomicAdd(&g_loss, (unsigned long long)csum);
        __threadfence();
        unsigned int old = atomicInc(&g_done, NBLK - 1);
        if (old == NBLK - 1) {
            unsigned long long tot = atomicAdd(&g_loss, 0ull);
            out[OFF_LOSS] = (float)((double)tot
                          / (16777216.0 * (double)N_ROWS * (double)D));
        }
    }
}

extern "C" void kernel_launch(void* const* d_in, const int* in_sizes, int n_in,
                              void* d_out, int out_size) {
    const float* x   = (const float*)d_in[0];   // [8,4096,64]
    const float* emb = (const float*)d_in[1];   // [64,1024]
    float* out = (float*)d_out;

    cudaFuncSetAttribute(vq_mma, cudaFuncAttributeMaxDynamicSharedMemorySize,
                         SMEM_SZ);
    prep_all<<<64, 256>>>(emb);
    vq_mma<<<NBLK, NTHR, SMEM_SZ>>>(x, out);
}